// round 4
// baseline (speedup 1.0000x reference)
#include <cuda_runtime.h>
#include <math.h>

#define BB 16
#define NAT 256
#define KNN 24
#define FF 128
#define LL 4
#define EPSC 0.01f
#define NNODE (BB*NAT)
#define NEDGE (NNODE*KNN)

typedef unsigned long long u64;

__device__ __forceinline__ u64 pk2(float lo, float hi) {
    u64 d; asm("mov.b64 %0, {%1,%2};" : "=l"(d) : "f"(lo), "f"(hi)); return d;
}
__device__ __forceinline__ u64 ffma2(u64 a, u64 b, u64 c) {
    u64 d; asm("fma.rn.f32x2 %0, %1, %2, %3;" : "=l"(d) : "l"(a), "l"(b), "l"(c)); return d;
}
__device__ __forceinline__ float2 up2(u64 a) {
    float2 r; asm("mov.b64 {%0,%1}, %2;" : "=f"(r.x), "=f"(r.y) : "l"(a)); return r;
}

// ---------------- scratch (device globals; no allocation allowed) ----------------
__device__ float g_x[NNODE*3];
__device__ int   g_idx[NEDGE];
__device__ float g_h0[NNODE*FF];
__device__ float g_h1[NNODE*FF];
__device__ float g_vec[NEDGE*3];
__device__ float g_dist[NEDGE];
__device__ float g_u[NEDGE*3];
__device__ unsigned char g_mask[NNODE*KNN*KNN];
__device__ float g_xcart[NNODE*3];
__device__ float g_strain[BB*6];   // symmetric 3x3 packed: 00,01,02,11,12,22
__device__ float g_tri[BB*6];
__device__ float g_cell[BB*9];     // geo_cell (row-major)
__device__ float g_rho[BB*9];      // action_rho
__device__ float g_invcell[BB*9];

__constant__ int c_pc[6] = {0,0,0,1,1,2};
__constant__ int c_pd[6] = {0,1,2,1,2,2};

__device__ __forceinline__ float siluf(float a) {
    return a / (1.f + expf(-a));
}

// ---------------- init: x = mod(x,1), cells = I, accumulators = 0, traj = 0 ----------------
__global__ void k_init(const float* __restrict__ x_in, float* __restrict__ out) {
    int i = blockIdx.x * blockDim.x + threadIdx.x;
    if (i < NNODE*3) { float v = x_in[i]; g_x[i] = v - floorf(v); out[i] = 0.f; }
    if (i < BB*9) {
        float id = ((i % 9) % 4 == 0) ? 1.f : 0.f;
        g_cell[i] = id; g_rho[i] = id;
    }
    if (i < BB*6) { g_strain[i] = 0.f; g_tri[i] = 0.f; }
}

// ---------------- kNN (periodic min-image, cell = I), exact top_k tie-break ----------------
__global__ void k_knn() {
    int b = blockIdx.x >> 8;
    int i = blockIdx.x & 255;
    __shared__ float sx[NAT*3];
    __shared__ float sd[NAT];
    int t = threadIdx.x;
    for (int q = t; q < NAT*3; q += 256) sx[q] = g_x[b*NAT*3 + q];
    __syncthreads();
    float xi0 = sx[i*3+0], xi1 = sx[i*3+1], xi2 = sx[i*3+2];
    float d0 = sx[t*3+0] - xi0; d0 -= rintf(d0);
    float d1 = sx[t*3+1] - xi1; d1 -= rintf(d1);
    float d2 = sx[t*3+2] - xi2; d2 -= rintf(d2);
    float d = sqrtf(d0*d0 + d1*d1 + d2*d2);
    if (t == i) d += 1e6f;
    sd[t] = d;
    __syncthreads();
    int rank = 0;
    float dt = d;
    for (int j = 0; j < NAT; j++) {
        float dj = sd[j];
        rank += (dj < dt) || (dj == dt && j < t);
    }
    if (rank < KNN) g_idx[(b*NAT + i)*KNN + rank] = t;
}

// ---------------- edge vectors: vec = (frac - round(frac)) @ cell ----------------
__global__ void k_edges() {
    int e = blockIdx.x * blockDim.x + threadIdx.x;
    if (e >= NEDGE) return;
    int b = e / (NAT*KNN);
    int n = (e / KNN) & 255;
    int j = g_idx[e];
    const float* xb = g_x + b*NAT*3;
    float f0 = xb[j*3+0] - xb[n*3+0]; f0 -= rintf(f0);
    float f1 = xb[j*3+1] - xb[n*3+1]; f1 -= rintf(f1);
    float f2 = xb[j*3+2] - xb[n*3+2]; f2 -= rintf(f2);
    const float* C = g_cell + b*9;
    float v0 = f0*C[0] + f1*C[3] + f2*C[6];
    float v1 = f0*C[1] + f1*C[4] + f2*C[7];
    float v2 = f0*C[2] + f1*C[5] + f2*C[8];
    float d  = sqrtf(v0*v0 + v1*v1 + v2*v2);
    g_vec[e*3+0] = v0; g_vec[e*3+1] = v1; g_vec[e*3+2] = v2;
    g_dist[e] = d;
    float inv = 1.f / (d + 1e-12f);
    g_u[e*3+0] = v0*inv; g_u[e*3+1] = v1*inv; g_u[e*3+2] = v2*inv;
}

// ---------------- triplet mask from INITIAL u (fixed thereafter) ----------------
__global__ void k_mask() {
    int node = blockIdx.x;
    __shared__ float su[KNN*3];
    int t = threadIdx.x;  // 64
    if (t < KNN*3) su[t] = g_u[node*KNN*3 + t];
    __syncthreads();
    for (int p = t; p < KNN*KNN; p += 64) {
        int jj = p / KNN, kk = p % KNN;
        const float* a = su + jj*3;
        const float* c = su + kk*3;
        float c0 = a[1]*c[2] - a[2]*c[1];
        float c1 = a[2]*c[0] - a[0]*c[2];
        float c2 = a[0]*c[1] - a[1]*c[0];
        g_mask[node*KNN*KNN + p] = (sqrtf(c0*c0 + c1*c1 + c2*c2) > 1e-3f) ? 1 : 0;
    }
}

// ---------------- embedding lookup ----------------
__global__ void k_embed(const float* __restrict__ emb, const int* __restrict__ z) {
    int i = blockIdx.x * blockDim.x + threadIdx.x;
    if (i >= NNODE*FF) return;
    int node = i / FF;
    g_h0[i] = emb[z[node]*FF + (i % FF)];
}

// ---------------- MPNN layer: h' = h + silu( (sum_k silu([h_j,dist]@W1+b1)) @ W2 + b2 ) ----
// Inner loops use packed fp32x2 FMA (FFMA2): acc2[k] holds (even-f partial, odd-f partial).
__global__ void __launch_bounds__(128) k_mpnn(
    const float* __restrict__ W1, const float* __restrict__ b1,
    const float* __restrict__ W2, const float* __restrict__ b2, int src)
{
    const float* hsrc = src ? g_h1 : g_h0;
    float*       hdst = src ? g_h0 : g_h1;
    int node = blockIdx.x;
    int b = node >> 8;
    int t = threadIdx.x;  // output feature g

    __shared__ float sh_hj[KNN*FF];   // [k][f], 16B-aligned rows
    __shared__ float sh_dist[KNN];
    __shared__ float sh_msum[FF];

    const int* ip = g_idx + node*KNN;
    #pragma unroll 4
    for (int k = 0; k < KNN; k++) {
        int j = ip[k];
        sh_hj[k*FF + t] = hsrc[(b*NAT + j)*FF + t];
    }
    if (t < KNN) sh_dist[t] = g_dist[node*KNN + t];
    __syncthreads();

    u64 acc2[KNN];
    #pragma unroll
    for (int k = 0; k < KNN; k++) acc2[k] = 0ULL;

    #pragma unroll 2
    for (int f = 0; f < FF; f += 4) {
        u64 w01 = pk2(W1[(f+0)*FF + t], W1[(f+1)*FF + t]);
        u64 w23 = pk2(W1[(f+2)*FF + t], W1[(f+3)*FF + t]);
        #pragma unroll
        for (int k = 0; k < KNN; k++) {
            ulonglong2 hp = *(const ulonglong2*)(sh_hj + k*FF + f);
            acc2[k] = ffma2(hp.x, w01, acc2[k]);
            acc2[k] = ffma2(hp.y, w23, acc2[k]);
        }
    }
    float wl = W1[FF*FF + t];  // dist row (f = 128)
    float bg = b1[t];
    float msum = 0.f;
    #pragma unroll
    for (int k = 0; k < KNN; k++) {
        float2 p = up2(acc2[k]);
        float a = bg + p.x + p.y + sh_dist[k]*wl;
        msum += siluf(a);
    }
    sh_msum[t] = msum;
    __syncthreads();

    u64 a2a = 0ULL, a2b = 0ULL;
    #pragma unroll 4
    for (int f = 0; f < FF; f += 4) {
        u64 w01 = pk2(W2[(f+0)*FF + t], W2[(f+1)*FF + t]);
        u64 w23 = pk2(W2[(f+2)*FF + t], W2[(f+3)*FF + t]);
        ulonglong2 mp = *(const ulonglong2*)(sh_msum + f);
        a2a = ffma2(mp.x, w01, a2a);
        a2b = ffma2(mp.y, w23, a2b);
    }
    float2 pa = up2(a2a), pb = up2(a2b);
    float a2 = b2[t] + pa.x + pa.y + pb.x + pb.y;
    float hv = hsrc[node*FF + t];
    hdst[node*FF + t] = hv + siluf(a2);
}

// ---------------- edge weights + strain/tri partials + x_cart ----------------
__global__ void __launch_bounds__(128) k_edgew(
    const float* __restrict__ awe, const float* __restrict__ awp, int hb)
{
    const float* h = hb ? g_h1 : g_h0;
    int node = blockIdx.x;
    int b = node >> 8;
    int t = threadIdx.x;
    int lane = t & 31, w = t >> 5;

    __shared__ float sh_hi[FF], sh_awe[FF], sh_awp[FF];
    __shared__ float sh_we[KNN], sh_wp[KNN];
    __shared__ float su[KNN*3], sv[KNN*3];
    __shared__ float sT[6];

    sh_hi[t]  = h[node*FF + t];
    sh_awe[t] = awe[t];
    sh_awp[t] = awp[t];
    if (t < KNN*3) { su[t] = g_u[node*KNN*3 + t]; sv[t] = g_vec[node*KNN*3 + t]; }
    if (t < 6) sT[t] = 0.f;
    __syncthreads();

    // w_e, w_p : each warp handles 6 edges, 32-lane dot over F
    #pragma unroll
    for (int q = 0; q < 6; q++) {
        int k = w*6 + q;
        int j = g_idx[node*KNN + k];
        const float* hj = h + (b*NAT + j)*FF;
        float de = 0.f, dp = 0.f;
        #pragma unroll
        for (int m = 0; m < 4; m++) {
            int f = lane + 32*m;
            float e = sh_hi[f] + hj[f];
            de += e * sh_awe[f];
            dp += e * sh_awp[f];
        }
        #pragma unroll
        for (int o = 16; o; o >>= 1) {
            de += __shfl_xor_sync(0xffffffffu, de, o);
            dp += __shfl_xor_sync(0xffffffffu, dp, o);
        }
        if (lane == 0) { sh_we[k] = tanhf(de); sh_wp[k] = tanhf(dp); }
    }
    __syncthreads();

    // strain partial (symmetric 6) and x_cart
    if (t < 6) {
        int c = c_pc[t], d = c_pd[t];
        float s = 0.f;
        #pragma unroll
        for (int k = 0; k < KNN; k++) s += sh_we[k] * su[k*3+c] * su[k*3+d];
        atomicAdd(&g_strain[b*6 + t], s);
    } else if (t >= 16 && t < 19) {
        int c = t - 16;
        float s = 0.f;
        #pragma unroll
        for (int k = 0; k < KNN; k++) s += sh_wp[k] * sv[k*3+c];
        g_xcart[node*3 + c] = EPSC * s;
    }

    // tri partial over 576 pairs (cross products on the fly, symmetric 6)
    float T0=0.f,T1=0.f,T2=0.f,T3=0.f,T4=0.f,T5=0.f;
    const unsigned char* mp = g_mask + node*KNN*KNN;
    for (int p = t; p < KNN*KNN; p += 128) {
        if (!mp[p]) continue;
        int jj = p / KNN, kk = p - jj*KNN;
        float wjk = sh_we[jj] * sh_we[kk];
        const float* a = su + jj*3;
        const float* c = su + kk*3;
        float c0 = a[1]*c[2] - a[2]*c[1];
        float c1 = a[2]*c[0] - a[0]*c[2];
        float c2 = a[0]*c[1] - a[1]*c[0];
        T0 += wjk*c0*c0; T1 += wjk*c0*c1; T2 += wjk*c0*c2;
        T3 += wjk*c1*c1; T4 += wjk*c1*c2; T5 += wjk*c2*c2;
    }
    #pragma unroll
    for (int o = 16; o; o >>= 1) {
        T0 += __shfl_xor_sync(0xffffffffu, T0, o);
        T1 += __shfl_xor_sync(0xffffffffu, T1, o);
        T2 += __shfl_xor_sync(0xffffffffu, T2, o);
        T3 += __shfl_xor_sync(0xffffffffu, T3, o);
        T4 += __shfl_xor_sync(0xffffffffu, T4, o);
        T5 += __shfl_xor_sync(0xffffffffu, T5, o);
    }
    if (lane == 0) {
        atomicAdd(&sT[0], T0); atomicAdd(&sT[1], T1); atomicAdd(&sT[2], T2);
        atomicAdd(&sT[3], T3); atomicAdd(&sT[4], T4); atomicAdd(&sT[5], T5);
    }
    __syncthreads();
    if (t < 6) atomicAdd(&g_tri[b*6 + t], sT[t]);
}

// ---------------- per-batch action update; inv(old cell); zero accumulators ----------------
__global__ void k_action(int is_last, float* __restrict__ out) {
    int b = blockIdx.x;
    if (threadIdx.x != 0) return;
    float s6[6], t6[6];
    #pragma unroll
    for (int i = 0; i < 6; i++) {
        s6[i] = g_strain[b*6+i]; t6[i] = g_tri[b*6+i];
        g_strain[b*6+i] = 0.f;   g_tri[b*6+i] = 0.f;
    }
    const float NK  = (float)(NAT*KNN);
    const float NKK = (float)(NAT*KNN*KNN);
    float P[9];
    P[0] = s6[0]/NK + t6[0]/NKK;
    P[1] = s6[1]/NK + t6[1]/NKK; P[3] = P[1];
    P[2] = s6[2]/NK + t6[2]/NKK; P[6] = P[2];
    P[4] = s6[3]/NK + t6[3]/NKK;
    P[5] = s6[4]/NK + t6[4]/NKK; P[7] = P[5];
    P[8] = s6[5]/NK + t6[5]/NKK;
    float A[9];
    #pragma unroll
    for (int i = 0; i < 9; i++) A[i] = EPSC*P[i] + ((i % 4 == 0) ? 1.f : 0.f);
    float R[9], C[9], Rn[9];
    #pragma unroll
    for (int i = 0; i < 9; i++) { R[i] = g_rho[b*9+i]; C[i] = g_cell[b*9+i]; }
    #pragma unroll
    for (int i = 0; i < 3; i++)
        #pragma unroll
        for (int k = 0; k < 3; k++)
            Rn[i*3+k] = A[i*3+0]*R[0+k] + A[i*3+1]*R[3+k] + A[i*3+2]*R[6+k];
    // inverse of OLD geo_cell (adjugate)
    float det = C[0]*(C[4]*C[8]-C[5]*C[7]) - C[1]*(C[3]*C[8]-C[5]*C[6]) + C[2]*(C[3]*C[7]-C[4]*C[6]);
    float id = 1.f/det;
    float IV[9];
    IV[0]=(C[4]*C[8]-C[5]*C[7])*id;
    IV[1]=(C[2]*C[7]-C[1]*C[8])*id;
    IV[2]=(C[1]*C[5]-C[2]*C[4])*id;
    IV[3]=(C[5]*C[6]-C[3]*C[8])*id;
    IV[4]=(C[0]*C[8]-C[2]*C[6])*id;
    IV[5]=(C[2]*C[3]-C[0]*C[5])*id;
    IV[6]=(C[3]*C[7]-C[4]*C[6])*id;
    IV[7]=(C[1]*C[6]-C[0]*C[7])*id;
    IV[8]=(C[0]*C[4]-C[1]*C[3])*id;
    #pragma unroll
    for (int i = 0; i < 9; i++) {
        g_invcell[b*9+i] = IV[i];
        g_rho[b*9+i] = Rn[i];
        g_cell[b*9+i] = Rn[i];   // geo_cell = rho_prime (cell0 = I)
    }
    if (is_last) {
        #pragma unroll
        for (int i = 0; i < 9; i++) out[NNODE*3 + b*9 + i] = Rn[i];
    }
}

// ---------------- position update: x += x_cart @ inv(old cell); traj += x_cart ----------------
__global__ void k_pos(float* __restrict__ out) {
    int node = blockIdx.x * blockDim.x + threadIdx.x;
    if (node >= NNODE) return;
    int b = node >> 8;
    float xc0 = g_xcart[node*3+0];
    float xc1 = g_xcart[node*3+1];
    float xc2 = g_xcart[node*3+2];
    const float* iv = g_invcell + b*9;
    float xf0 = xc0*iv[0] + xc1*iv[3] + xc2*iv[6];
    float xf1 = xc0*iv[1] + xc1*iv[4] + xc2*iv[7];
    float xf2 = xc0*iv[2] + xc1*iv[5] + xc2*iv[8];
    g_x[node*3+0] += xf0;
    g_x[node*3+1] += xf1;
    g_x[node*3+2] += xf2;
    out[node*3+0] += xc0;
    out[node*3+1] += xc1;
    out[node*3+2] += xc2;
}

// ---------------- launch ----------------
extern "C" void kernel_launch(void* const* d_in, const int* in_sizes, int n_in,
                              void* d_out, int out_size) {
    const float* x_in = (const float*)d_in[1];
    const int*   z    = (const int*)  d_in[2];
    const float* emb  = (const float*)d_in[4];
    const float* mW1  = (const float*)d_in[5];
    const float* mb1  = (const float*)d_in[6];
    const float* mW2  = (const float*)d_in[7];
    const float* mb2  = (const float*)d_in[8];
    const float* uW1  = (const float*)d_in[9];
    const float* ub1  = (const float*)d_in[10];
    const float* uW2  = (const float*)d_in[11];
    const float* ub2  = (const float*)d_in[12];
    const float* awe  = (const float*)d_in[13];
    const float* awp  = (const float*)d_in[14];
    float* out = (float*)d_out;

    k_init <<<48, 256>>>(x_in, out);
    k_knn  <<<NNODE, 256>>>();
    k_edges<<<(NEDGE + 255)/256, 256>>>();
    k_mask <<<NNODE, 64>>>();
    k_embed<<<(NNODE*FF + 255)/256, 256>>>(emb, z);

    int src = 0;
    for (int l = 0; l < LL; l++) {
        k_mpnn<<<NNODE, 128>>>(mW1 + l*(FF+1)*FF, mb1 + l*FF, mW2 + l*FF*FF, mb2 + l*FF, src);
        src ^= 1;
    }
    for (int l = 0; l < LL; l++) {
        k_mpnn<<<NNODE, 128>>>(uW1 + l*(FF+1)*FF, ub1 + l*FF, uW2 + l*FF*FF, ub2 + l*FF, src);
        src ^= 1;
        k_edgew<<<NNODE, 128>>>(awe + l*FF, awp + l*FF, src);
        k_action<<<BB, 32>>>(l == LL-1 ? 1 : 0, out);
        k_pos  <<<(NNODE + 255)/256, 256>>>(out);
        if (l < LL-1) k_edges<<<(NEDGE + 255)/256, 256>>>();
    }
}

// round 5
// speedup vs baseline: 2.4370x; 2.4370x over previous
#include <cuda_runtime.h>
#include <math.h>

#define BB 16
#define NAT 256
#define KNN 24
#define FF 128
#define LL 4
#define EPSC 0.01f
#define NNODE (BB*NAT)
#define NEDGE (NNODE*KNN)
#define MT 16   // nodes per GEMM tile block

// ---------------- scratch (device globals; no allocation allowed) ----------------
__device__ float g_x[NNODE*3];
__device__ int   g_idx[NEDGE];
__device__ float g_h[NNODE*FF];
__device__ float g_y[NNODE*FF];      // per-node W1 transform (pre-silu, pre-dist)
__device__ float g_msum[NNODE*FF];   // aggregated edge messages
__device__ float g_vec[NEDGE*3];
__device__ float g_dist[NEDGE];
__device__ float g_u[NEDGE*3];
__device__ unsigned char g_mask[NNODE*KNN*KNN];
__device__ float g_xcart[NNODE*3];
__device__ float g_strain[BB*6];   // symmetric 3x3 packed: 00,01,02,11,12,22
__device__ float g_tri[BB*6];
__device__ float g_cell[BB*9];     // geo_cell (row-major)
__device__ float g_rho[BB*9];      // action_rho
__device__ float g_invcell[BB*9];

__constant__ int c_pc[6] = {0,0,0,1,1,2};
__constant__ int c_pd[6] = {0,1,2,1,2,2};

__device__ __forceinline__ float siluf(float a) {
    return a / (1.f + expf(-a));
}

// ---------------- init: x = mod(x,1), cells = I, accumulators = 0, traj = 0 ----------------
__global__ void k_init(const float* __restrict__ x_in, float* __restrict__ out) {
    int i = blockIdx.x * blockDim.x + threadIdx.x;
    if (i < NNODE*3) { float v = x_in[i]; g_x[i] = v - floorf(v); out[i] = 0.f; }
    if (i < BB*9) {
        float id = ((i % 9) % 4 == 0) ? 1.f : 0.f;
        g_cell[i] = id; g_rho[i] = id;
    }
    if (i < BB*6) { g_strain[i] = 0.f; g_tri[i] = 0.f; }
}

// ---------------- kNN (periodic min-image, cell = I), exact top_k tie-break ----------------
__global__ void k_knn() {
    int b = blockIdx.x >> 8;
    int i = blockIdx.x & 255;
    __shared__ float sx[NAT*3];
    __shared__ float sd[NAT];
    int t = threadIdx.x;
    for (int q = t; q < NAT*3; q += 256) sx[q] = g_x[b*NAT*3 + q];
    __syncthreads();
    float xi0 = sx[i*3+0], xi1 = sx[i*3+1], xi2 = sx[i*3+2];
    float d0 = sx[t*3+0] - xi0; d0 -= rintf(d0);
    float d1 = sx[t*3+1] - xi1; d1 -= rintf(d1);
    float d2 = sx[t*3+2] - xi2; d2 -= rintf(d2);
    float d = sqrtf(d0*d0 + d1*d1 + d2*d2);
    if (t == i) d += 1e6f;
    sd[t] = d;
    __syncthreads();
    int rank = 0;
    float dt = d;
    for (int j = 0; j < NAT; j++) {
        float dj = sd[j];
        rank += (dj < dt) || (dj == dt && j < t);
    }
    if (rank < KNN) g_idx[(b*NAT + i)*KNN + rank] = t;
}

// ---------------- edge vectors: vec = (frac - round(frac)) @ cell ----------------
__global__ void k_edges() {
    int e = blockIdx.x * blockDim.x + threadIdx.x;
    if (e >= NEDGE) return;
    int b = e / (NAT*KNN);
    int n = (e / KNN) & 255;
    int j = g_idx[e];
    const float* xb = g_x + b*NAT*3;
    float f0 = xb[j*3+0] - xb[n*3+0]; f0 -= rintf(f0);
    float f1 = xb[j*3+1] - xb[n*3+1]; f1 -= rintf(f1);
    float f2 = xb[j*3+2] - xb[n*3+2]; f2 -= rintf(f2);
    const float* C = g_cell + b*9;
    float v0 = f0*C[0] + f1*C[3] + f2*C[6];
    float v1 = f0*C[1] + f1*C[4] + f2*C[7];
    float v2 = f0*C[2] + f1*C[5] + f2*C[8];
    float d  = sqrtf(v0*v0 + v1*v1 + v2*v2);
    g_vec[e*3+0] = v0; g_vec[e*3+1] = v1; g_vec[e*3+2] = v2;
    g_dist[e] = d;
    float inv = 1.f / (d + 1e-12f);
    g_u[e*3+0] = v0*inv; g_u[e*3+1] = v1*inv; g_u[e*3+2] = v2*inv;
}

// ---------------- triplet mask from INITIAL u (fixed thereafter) ----------------
__global__ void k_mask() {
    int node = blockIdx.x;
    __shared__ float su[KNN*3];
    int t = threadIdx.x;  // 64
    if (t < KNN*3) su[t] = g_u[node*KNN*3 + t];
    __syncthreads();
    for (int p = t; p < KNN*KNN; p += 64) {
        int jj = p / KNN, kk = p % KNN;
        const float* a = su + jj*3;
        const float* c = su + kk*3;
        float c0 = a[1]*c[2] - a[2]*c[1];
        float c1 = a[2]*c[0] - a[0]*c[2];
        float c2 = a[0]*c[1] - a[1]*c[0];
        g_mask[node*KNN*KNN + p] = (sqrtf(c0*c0 + c1*c1 + c2*c2) > 1e-3f) ? 1 : 0;
    }
}

// ---------------- embedding lookup ----------------
__global__ void k_embed(const float* __restrict__ emb, const int* __restrict__ z) {
    int i = blockIdx.x * blockDim.x + threadIdx.x;
    if (i >= NNODE*FF) return;
    int node = i / FF;
    g_h[i] = emb[z[node]*FF + (i % FF)];
}

// ---------------- lin1: y = h @ W1[:128,:] + b1 (per-node part of edge MLP) ----------------
__global__ void __launch_bounds__(128) k_lin1(
    const float* __restrict__ W1, const float* __restrict__ b1)
{
    int t = threadIdx.x;
    int base = blockIdx.x * MT;
    __shared__ float sh[MT*FF];
    #pragma unroll
    for (int m = 0; m < MT; m++) sh[m*FF + t] = g_h[(base + m)*FF + t];
    __syncthreads();

    float acc[MT];
    float bg = b1[t];
    #pragma unroll
    for (int m = 0; m < MT; m++) acc[m] = bg;

    #pragma unroll 2
    for (int f = 0; f < FF; f += 4) {
        float w0 = W1[(f+0)*FF + t];
        float w1 = W1[(f+1)*FF + t];
        float w2 = W1[(f+2)*FF + t];
        float w3 = W1[(f+3)*FF + t];
        #pragma unroll
        for (int m = 0; m < MT; m++) {
            float4 hv = *(const float4*)(sh + m*FF + f);
            acc[m] += hv.x*w0 + hv.y*w1 + hv.z*w2 + hv.w*w3;
        }
    }
    #pragma unroll
    for (int m = 0; m < MT; m++) g_y[(base + m)*FF + t] = acc[m];
}

// ---------------- aggr: msum = sum_k silu(y[j_k] + dist_k * W1[128,:]) ----------------
__global__ void __launch_bounds__(128) k_aggr(const float* __restrict__ W1)
{
    int node = blockIdx.x;
    int b = node >> 8;
    int t = threadIdx.x;
    __shared__ float sd[KNN];
    __shared__ int   sj[KNN];
    if (t < KNN) { sd[t] = g_dist[node*KNN + t]; sj[t] = g_idx[node*KNN + t]; }
    __syncthreads();
    float wl = W1[FF*FF + t];
    float s = 0.f;
    #pragma unroll 4
    for (int k = 0; k < KNN; k++) {
        float yv = g_y[(b*NAT + sj[k])*FF + t];
        s += siluf(yv + sd[k]*wl);
    }
    g_msum[node*FF + t] = s;
}

// ---------------- lin2: h += silu(msum @ W2 + b2) (in-place, node-local) ----------------
__global__ void __launch_bounds__(128) k_lin2(
    const float* __restrict__ W2, const float* __restrict__ b2)
{
    int t = threadIdx.x;
    int base = blockIdx.x * MT;
    __shared__ float sh[MT*FF];
    #pragma unroll
    for (int m = 0; m < MT; m++) sh[m*FF + t] = g_msum[(base + m)*FF + t];
    __syncthreads();

    float acc[MT];
    float bg = b2[t];
    #pragma unroll
    for (int m = 0; m < MT; m++) acc[m] = bg;

    #pragma unroll 2
    for (int f = 0; f < FF; f += 4) {
        float w0 = W2[(f+0)*FF + t];
        float w1 = W2[(f+1)*FF + t];
        float w2 = W2[(f+2)*FF + t];
        float w3 = W2[(f+3)*FF + t];
        #pragma unroll
        for (int m = 0; m < MT; m++) {
            float4 mv = *(const float4*)(sh + m*FF + f);
            acc[m] += mv.x*w0 + mv.y*w1 + mv.z*w2 + mv.w*w3;
        }
    }
    #pragma unroll
    for (int m = 0; m < MT; m++) {
        int o = (base + m)*FF + t;
        g_h[o] = g_h[o] + siluf(acc[m]);
    }
}

// ---------------- edge weights + strain/tri partials + x_cart ----------------
__global__ void __launch_bounds__(128) k_edgew(
    const float* __restrict__ awe, const float* __restrict__ awp)
{
    const float* h = g_h;
    int node = blockIdx.x;
    int b = node >> 8;
    int t = threadIdx.x;
    int lane = t & 31, w = t >> 5;

    __shared__ float sh_hi[FF], sh_awe[FF], sh_awp[FF];
    __shared__ float sh_we[KNN], sh_wp[KNN];
    __shared__ float su[KNN*3], sv[KNN*3];
    __shared__ float sT[6];

    sh_hi[t]  = h[node*FF + t];
    sh_awe[t] = awe[t];
    sh_awp[t] = awp[t];
    if (t < KNN*3) { su[t] = g_u[node*KNN*3 + t]; sv[t] = g_vec[node*KNN*3 + t]; }
    if (t < 6) sT[t] = 0.f;
    __syncthreads();

    // w_e, w_p : each warp handles 6 edges, 32-lane dot over F
    #pragma unroll
    for (int q = 0; q < 6; q++) {
        int k = w*6 + q;
        int j = g_idx[node*KNN + k];
        const float* hj = h + (b*NAT + j)*FF;
        float de = 0.f, dp = 0.f;
        #pragma unroll
        for (int m = 0; m < 4; m++) {
            int f = lane + 32*m;
            float e = sh_hi[f] + hj[f];
            de += e * sh_awe[f];
            dp += e * sh_awp[f];
        }
        #pragma unroll
        for (int o = 16; o; o >>= 1) {
            de += __shfl_xor_sync(0xffffffffu, de, o);
            dp += __shfl_xor_sync(0xffffffffu, dp, o);
        }
        if (lane == 0) { sh_we[k] = tanhf(de); sh_wp[k] = tanhf(dp); }
    }
    __syncthreads();

    // strain partial (symmetric 6) and x_cart
    if (t < 6) {
        int c = c_pc[t], d = c_pd[t];
        float s = 0.f;
        #pragma unroll
        for (int k = 0; k < KNN; k++) s += sh_we[k] * su[k*3+c] * su[k*3+d];
        atomicAdd(&g_strain[b*6 + t], s);
    } else if (t >= 16 && t < 19) {
        int c = t - 16;
        float s = 0.f;
        #pragma unroll
        for (int k = 0; k < KNN; k++) s += sh_wp[k] * sv[k*3+c];
        g_xcart[node*3 + c] = EPSC * s;
    }

    // tri partial over 576 pairs (cross products on the fly, symmetric 6)
    float T0=0.f,T1=0.f,T2=0.f,T3=0.f,T4=0.f,T5=0.f;
    const unsigned char* mp = g_mask + node*KNN*KNN;
    for (int p = t; p < KNN*KNN; p += 128) {
        if (!mp[p]) continue;
        int jj = p / KNN, kk = p - jj*KNN;
        float wjk = sh_we[jj] * sh_we[kk];
        const float* a = su + jj*3;
        const float* c = su + kk*3;
        float c0 = a[1]*c[2] - a[2]*c[1];
        float c1 = a[2]*c[0] - a[0]*c[2];
        float c2 = a[0]*c[1] - a[1]*c[0];
        T0 += wjk*c0*c0; T1 += wjk*c0*c1; T2 += wjk*c0*c2;
        T3 += wjk*c1*c1; T4 += wjk*c1*c2; T5 += wjk*c2*c2;
    }
    #pragma unroll
    for (int o = 16; o; o >>= 1) {
        T0 += __shfl_xor_sync(0xffffffffu, T0, o);
        T1 += __shfl_xor_sync(0xffffffffu, T1, o);
        T2 += __shfl_xor_sync(0xffffffffu, T2, o);
        T3 += __shfl_xor_sync(0xffffffffu, T3, o);
        T4 += __shfl_xor_sync(0xffffffffu, T4, o);
        T5 += __shfl_xor_sync(0xffffffffu, T5, o);
    }
    if (lane == 0) {
        atomicAdd(&sT[0], T0); atomicAdd(&sT[1], T1); atomicAdd(&sT[2], T2);
        atomicAdd(&sT[3], T3); atomicAdd(&sT[4], T4); atomicAdd(&sT[5], T5);
    }
    __syncthreads();
    if (t < 6) atomicAdd(&g_tri[b*6 + t], sT[t]);
}

// ---------------- per-batch action update; inv(old cell); zero accumulators ----------------
__global__ void k_action(int is_last, float* __restrict__ out) {
    int b = blockIdx.x;
    if (threadIdx.x != 0) return;
    float s6[6], t6[6];
    #pragma unroll
    for (int i = 0; i < 6; i++) {
        s6[i] = g_strain[b*6+i]; t6[i] = g_tri[b*6+i];
        g_strain[b*6+i] = 0.f;   g_tri[b*6+i] = 0.f;
    }
    const float NK  = (float)(NAT*KNN);
    const float NKK = (float)(NAT*KNN*KNN);
    float P[9];
    P[0] = s6[0]/NK + t6[0]/NKK;
    P[1] = s6[1]/NK + t6[1]/NKK; P[3] = P[1];
    P[2] = s6[2]/NK + t6[2]/NKK; P[6] = P[2];
    P[4] = s6[3]/NK + t6[3]/NKK;
    P[5] = s6[4]/NK + t6[4]/NKK; P[7] = P[5];
    P[8] = s6[5]/NK + t6[5]/NKK;
    float A[9];
    #pragma unroll
    for (int i = 0; i < 9; i++) A[i] = EPSC*P[i] + ((i % 4 == 0) ? 1.f : 0.f);
    float R[9], C[9], Rn[9];
    #pragma unroll
    for (int i = 0; i < 9; i++) { R[i] = g_rho[b*9+i]; C[i] = g_cell[b*9+i]; }
    #pragma unroll
    for (int i = 0; i < 3; i++)
        #pragma unroll
        for (int k = 0; k < 3; k++)
            Rn[i*3+k] = A[i*3+0]*R[0+k] + A[i*3+1]*R[3+k] + A[i*3+2]*R[6+k];
    // inverse of OLD geo_cell (adjugate)
    float det = C[0]*(C[4]*C[8]-C[5]*C[7]) - C[1]*(C[3]*C[8]-C[5]*C[6]) + C[2]*(C[3]*C[7]-C[4]*C[6]);
    float id = 1.f/det;
    float IV[9];
    IV[0]=(C[4]*C[8]-C[5]*C[7])*id;
    IV[1]=(C[2]*C[7]-C[1]*C[8])*id;
    IV[2]=(C[1]*C[5]-C[2]*C[4])*id;
    IV[3]=(C[5]*C[6]-C[3]*C[8])*id;
    IV[4]=(C[0]*C[8]-C[2]*C[6])*id;
    IV[5]=(C[2]*C[3]-C[0]*C[5])*id;
    IV[6]=(C[3]*C[7]-C[4]*C[6])*id;
    IV[7]=(C[1]*C[6]-C[0]*C[7])*id;
    IV[8]=(C[0]*C[4]-C[1]*C[3])*id;
    #pragma unroll
    for (int i = 0; i < 9; i++) {
        g_invcell[b*9+i] = IV[i];
        g_rho[b*9+i] = Rn[i];
        g_cell[b*9+i] = Rn[i];   // geo_cell = rho_prime (cell0 = I)
    }
    if (is_last) {
        #pragma unroll
        for (int i = 0; i < 9; i++) out[NNODE*3 + b*9 + i] = Rn[i];
    }
}

// ---------------- position update: x += x_cart @ inv(old cell); traj += x_cart ----------------
__global__ void k_pos(float* __restrict__ out) {
    int node = blockIdx.x * blockDim.x + threadIdx.x;
    if (node >= NNODE) return;
    int b = node >> 8;
    float xc0 = g_xcart[node*3+0];
    float xc1 = g_xcart[node*3+1];
    float xc2 = g_xcart[node*3+2];
    const float* iv = g_invcell + b*9;
    float xf0 = xc0*iv[0] + xc1*iv[3] + xc2*iv[6];
    float xf1 = xc0*iv[1] + xc1*iv[4] + xc2*iv[7];
    float xf2 = xc0*iv[2] + xc1*iv[5] + xc2*iv[8];
    g_x[node*3+0] += xf0;
    g_x[node*3+1] += xf1;
    g_x[node*3+2] += xf2;
    out[node*3+0] += xc0;
    out[node*3+1] += xc1;
    out[node*3+2] += xc2;
}

// ---------------- launch ----------------
extern "C" void kernel_launch(void* const* d_in, const int* in_sizes, int n_in,
                              void* d_out, int out_size) {
    const float* x_in = (const float*)d_in[1];
    const int*   z    = (const int*)  d_in[2];
    const float* emb  = (const float*)d_in[4];
    const float* mW1  = (const float*)d_in[5];
    const float* mb1  = (const float*)d_in[6];
    const float* mW2  = (const float*)d_in[7];
    const float* mb2  = (const float*)d_in[8];
    const float* uW1  = (const float*)d_in[9];
    const float* ub1  = (const float*)d_in[10];
    const float* uW2  = (const float*)d_in[11];
    const float* ub2  = (const float*)d_in[12];
    const float* awe  = (const float*)d_in[13];
    const float* awp  = (const float*)d_in[14];
    float* out = (float*)d_out;

    const int NG = NNODE / MT;  // 256 tiles

    k_init <<<48, 256>>>(x_in, out);
    k_knn  <<<NNODE, 256>>>();
    k_edges<<<(NEDGE + 255)/256, 256>>>();
    k_mask <<<NNODE, 64>>>();
    k_embed<<<(NNODE*FF + 255)/256, 256>>>(emb, z);

    for (int l = 0; l < LL; l++) {
        k_lin1<<<NG, 128>>>(mW1 + l*(FF+1)*FF, mb1 + l*FF);
        k_aggr<<<NNODE, 128>>>(mW1 + l*(FF+1)*FF);
        k_lin2<<<NG, 128>>>(mW2 + l*FF*FF, mb2 + l*FF);
    }
    for (int l = 0; l < LL; l++) {
        k_lin1<<<NG, 128>>>(uW1 + l*(FF+1)*FF, ub1 + l*FF);
        k_aggr<<<NNODE, 128>>>(uW1 + l*(FF+1)*FF);
        k_lin2<<<NG, 128>>>(uW2 + l*FF*FF, ub2 + l*FF);
        k_edgew<<<NNODE, 128>>>(awe + l*FF, awp + l*FF);
        k_action<<<BB, 32>>>(l == LL-1 ? 1 : 0, out);
        k_pos  <<<(NNODE + 255)/256, 256>>>(out);
        if (l < LL-1) k_edges<<<(NEDGE + 255)/256, 256>>>();
    }
}